// round 14
// baseline (speedup 1.0000x reference)
#include <cuda_runtime.h>

// Chamfer distance loss on (2,8,4096,3) fp32 clouds.
// Shared distance matrix (268M pairs): each pair updates the pred-side row-min
// and the targ-side col-min.  Min combining = atomicMax on inverted keys
// key = ~bits(max(d2,0)); identity 0 -> statically zero-init buffer; the
// reduce kernel re-zeroes slots after reading and its last block resets
// g_sum/g_done (stream-ordered for graph replay).
//
// Round-14: conflict-free warp layout. tx = tid&31 (32 target-pairs per
// warp-row), ty = tid>>5 (8 query groups, 64-query strips). Col smem ATOMS
// now hit 32 DISTINCT addresses per instruction (was 2-way collision), and
// per-chunk ATOMS bursts halve. Inner stream unchanged (8 slots / 2 pairs).

#define NPTS    4096
#define NBATCH  16
#define THREADS 256
#define GRID    296                     // 2 blocks/SM x 148
#define TC      512                     // targets per chunk
#define NCHUNK  (NBATCH * 64 * 8)       // 8192 chunks (64 qstrips x 8 tchunks)
#define NQTOT   (2 * NBATCH * NPTS)     // 131072
#define BIGF    3.4e38f

#define P2_BLOCKS 128
#define P2_THREADS 256

typedef unsigned long long ull;

__device__ unsigned g_key[NQTOT];       // zero-init; [0:65536)=pred rows, rest=targ cols
__device__ float    g_sum;              // zero-init; reset by reduce's last block
__device__ unsigned g_done;             // zero-init; reset by reduce's last block

__device__ __forceinline__ ull dupf(float v) {
    ull r; asm("mov.b64 %0, {%1, %1};" : "=l"(r) : "f"(v)); return r;
}
__device__ __forceinline__ ull pk(float lo, float hi) {
    ull r; asm("mov.b64 %0, {%1, %2};" : "=l"(r) : "f"(lo), "f"(hi)); return r;
}
__device__ __forceinline__ unsigned mkkey(float d2) {
    return ~__float_as_uint(fmaxf(d2, 0.0f));
}

// ---- launch 1: pairwise mins ----
__global__ void __launch_bounds__(THREADS, 2)
cd_main_kernel(const float* __restrict__ pred, const float* __restrict__ targ) {
    __shared__ __align__(16) float4 sA[TC / 2];   // (y0_t0,y0_t1,y1_t0,y1_t1)
    __shared__ __align__(16) float4 sB[TC / 2];   // (y2_t0,y2_t1, h_t0, h_t1)
    __shared__ unsigned scol[TC];

    const int tid = threadIdx.x;
    const int tx  = tid & 31;           // 32 target-pair groups (conflict-free)
    const int ty  = tid >> 5;           // 8 query groups
    const int bid = blockIdx.x;

    scol[tid] = 0u;                     // identity (both halves)
    scol[tid + 256] = 0u;

    const int c0 = (int)(((long long)bid       * NCHUNK) / GRID);
    const int c1 = (int)(((long long)(bid + 1) * NCHUNK) / GRID);

    ull  m0[8], m1[8], m2[8], x2d[8];   // duplicated-lane query state
    float ralo[8], rahi[8];             // row-min accumulators
    int cur_strip = -1, cur_qbase = 0;

    for (int cid = c0; cid < c1; cid++) {
        const int b  = cid >> 9;        // 512 chunks per batch (64 qs x 8 tc)
        const int rr = cid & 511;
        const int qs = rr >> 3;
        const int tc = rr & 7;

        // ---- query strip management: flush 8 row mins, load 8 new queries ----
        const int strip = (b << 6) | qs;
        if (strip != cur_strip) {
            if (cur_strip >= 0) {
#pragma unroll
                for (int i = 0; i < 8; i++)
                    atomicMax(&g_key[cur_qbase + (ty << 3) + i],
                              mkkey(fminf(ralo[i], rahi[i])));
            }
            cur_strip = strip;
            cur_qbase = (b << 12) + (qs << 6);
            // 8 points = 24 floats = 6 x float4 (96B, 16B-aligned)
            const float4* __restrict__ qv =
                (const float4*)(pred + (size_t)(cur_qbase + (ty << 3)) * 3);
            float4 f[6];
#pragma unroll
            for (int i = 0; i < 6; i++) f[i] = qv[i];
            const float* q = (const float*)f;
#pragma unroll
            for (int i = 0; i < 8; i++) {
                const float x0 = q[i * 3 + 0];
                const float x1 = q[i * 3 + 1];
                const float x2 = q[i * 3 + 2];
                m0[i]  = dupf(-2.0f * x0);
                m1[i]  = dupf(-2.0f * x1);
                m2[i]  = dupf(-2.0f * x2);
                x2d[i] = dupf(x0 * x0 + x1 * x1 + x2 * x2);
                ralo[i] = BIGF; rahi[i] = BIGF;
            }
        }

        // ---- fill target tile: 256 threads x 2 targets, interleaved float4 ----
        {
            const float* __restrict__ bp =
                targ + (size_t)((b << 12) + (tc << 9) + tid * 2) * 3;
            const float a0 = bp[0], a1 = bp[1], a2 = bp[2];
            const float b0 = bp[3], b1 = bp[4], b2 = bp[5];
            sA[tid] = make_float4(a0, b0, a1, b1);
            sB[tid] = make_float4(a2, b2,
                                  a0 * a0 + a1 * a1 + a2 * a2,
                                  b0 * b0 + b1 * b1 + b2 * b2);
        }
        __syncthreads();    // A: tile + scol(identity) visible

        // ---- main: 8 warp-rows x (32 target-pairs) x 8 queries ----
#pragma unroll
        for (int k = 0; k < 8; k++) {
            const int pw = tx + (k << 5);
            const float4 ua = sA[pw];     // LDS.128 (32 consecutive f4, no conflict)
            const float4 ub = sB[pw];     // LDS.128
            const ull y0p = pk(ua.x, ua.y);
            const ull y1p = pk(ua.z, ua.w);
            const ull y2p = pk(ub.x, ub.y);
            const ull hp  = pk(ub.z, ub.w);
            float clo = BIGF, chi = BIGF;
#pragma unroll
            for (int q = 0; q < 8; q++) {
                ull s, w;
                asm("add.rn.f32x2 %0, %1, %2;"     : "=l"(s) : "l"(x2d[q]), "l"(hp));
                asm("fma.rn.f32x2 %0, %1, %2, %3;" : "=l"(w) : "l"(m2[q]), "l"(y2p), "l"(s));
                asm("fma.rn.f32x2 %0, %1, %2, %3;" : "=l"(w) : "l"(m1[q]), "l"(y1p), "l"(w));
                asm("fma.rn.f32x2 %0, %1, %2, %3;" : "=l"(w) : "l"(m0[q]), "l"(y0p), "l"(w));
                float wl, wh;
                asm("mov.b64 {%0, %1}, %2;" : "=f"(wl), "=f"(wh) : "l"(w));
                ralo[q] = fminf(ralo[q], wl);
                rahi[q] = fminf(rahi[q], wh);
                clo = fminf(clo, wl);
                chi = fminf(chi, wh);
            }
            // in-loop, return-less col merges: 32 distinct addresses per warp
            const int w2 = (tx << 1) + (k << 6);
            atomicMax(&scol[w2],     mkkey(clo));
            atomicMax(&scol[w2 + 1], mkkey(chi));
        }
        __syncthreads();    // B: scol complete; tile reads done

        // ---- two global return-less atomicMax per thread; reset own slots ----
        const int gb = (NBATCH * NPTS) + (b << 12) + (tc << 9);
        atomicMax(&g_key[gb + tid],       scol[tid]);
        atomicMax(&g_key[gb + tid + 256], scol[tid + 256]);
        scol[tid] = 0u;
        scol[tid + 256] = 0u;
    }

    // final row flush
    if (cur_strip >= 0) {
#pragma unroll
        for (int i = 0; i < 8; i++)
            atomicMax(&g_key[cur_qbase + (ty << 3) + i],
                      mkkey(fminf(ralo[i], rahi[i])));
    }
}

// ---- launch 2: sqrt + mean; re-zeroes g_key; last block resets g_sum/g_done ----
__global__ void __launch_bounds__(P2_THREADS)
cd_reduce_kernel(float* __restrict__ out) {
    __shared__ float swsum[P2_THREADS / 32];
    const int tid = threadIdx.x;
    const int i = blockIdx.x * P2_THREADS + tid;     // 32768 threads, 1 uint4 each
    uint4* kp = reinterpret_cast<uint4*>(g_key);
    const uint4 kv = kp[i];
    float lsum = sqrtf(__uint_as_float(~kv.x)) + sqrtf(__uint_as_float(~kv.y))
               + sqrtf(__uint_as_float(~kv.z)) + sqrtf(__uint_as_float(~kv.w));
    kp[i] = make_uint4(0u, 0u, 0u, 0u);              // identity for next call
#pragma unroll
    for (int off = 16; off > 0; off >>= 1)
        lsum += __shfl_down_sync(0xFFFFFFFFu, lsum, off);
    const int lane = tid & 31;
    const int wid  = tid >> 5;
    if (lane == 0) swsum[wid] = lsum;
    __syncthreads();
    if (wid == 0) {
        float v = (lane < P2_THREADS / 32) ? swsum[lane] : 0.0f;
#pragma unroll
        for (int off = (P2_THREADS / 32) / 2; off > 0; off >>= 1)
            v += __shfl_down_sync(0xFFFFFFFFu, v, off);
        if (lane == 0) {
            atomicAdd(&g_sum, v);
            __threadfence();
            const unsigned rdone = atomicAdd(&g_done, 1u);
            if (rdone == P2_BLOCKS - 1) {
                out[0] = atomicAdd(&g_sum, 0.0f) * (1.0f / (float)(NBATCH * NPTS));
                g_sum = 0.0f;                        // reset for next replay
                g_done = 0u;
            }
        }
    }
}

extern "C" void kernel_launch(void* const* d_in, const int* in_sizes, int n_in,
                              void* d_out, int out_size) {
    const float* pred = (const float*)d_in[0];
    const float* targ = (const float*)d_in[1];
    float* out = (float*)d_out;
    cd_main_kernel<<<GRID, THREADS>>>(pred, targ);    // launch 1
    cd_reduce_kernel<<<P2_BLOCKS, P2_THREADS>>>(out); // launch 2
}

// round 15
// speedup vs baseline: 1.0483x; 1.0483x over previous
#include <cuda_runtime.h>

// Chamfer distance loss on (2,8,4096,3) fp32 clouds.
// Shared distance matrix (268M pairs): each pair updates the pred-side row-min
// and the targ-side col-min.  Min combining = atomicMax on inverted keys
// key = ~bits(max(d2,0)); identity 0 -> statically zero-init buffer; the
// reduce kernel re-zeroes slots after reading and its last block resets
// g_sum/g_done (stream-ordered for graph replay).
//
// Round-15: clean occupancy experiment. R13 schedule exactly (4096 chunks,
// 128-query strips, TC=512, same atomics/barriers), but queries are packed
// 2-per-f32x2 lane (32 query regs, was 64) and targets stored lane-duplicated
// in smem so packed operands load as aligned LDS.128 register pairs.
// ~70 regs -> 3 blocks/SM (6 warps/SMSP). Instruction mix per 2 pairs
// unchanged: 1 ADD2 + 3 FFMA2 + 4 FMNMX.

#define NPTS    4096
#define NBATCH  16
#define THREADS 256
#define GRID    444                     // 3 blocks/SM x 148
#define TC      512                     // targets per chunk
#define NCHUNK  (NBATCH * 32 * 8)       // 4096 chunks (32 qstrips x 8 tchunks)
#define NQTOT   (2 * NBATCH * NPTS)     // 131072
#define BIGF    3.4e38f

#define P2_BLOCKS 128
#define P2_THREADS 256

typedef unsigned long long ull;

__device__ unsigned g_key[NQTOT];       // zero-init; [0:65536)=pred rows, rest=targ cols
__device__ float    g_sum;              // zero-init; reset by reduce's last block
__device__ unsigned g_done;             // zero-init; reset by reduce's last block

__device__ __forceinline__ ull pk(float lo, float hi) {
    ull r; asm("mov.b64 %0, {%1, %2};" : "=l"(r) : "f"(lo), "f"(hi)); return r;
}
__device__ __forceinline__ unsigned mkkey(float d2) {
    return ~__float_as_uint(fmaxf(d2, 0.0f));
}

// ---- launch 1: pairwise mins ----
__global__ void __launch_bounds__(THREADS, 3)
cd_main_kernel(const float* __restrict__ pred, const float* __restrict__ targ) {
    __shared__ __align__(16) float4 s4a[TC];   // (y0,y0,y1,y1) per target
    __shared__ __align__(16) float4 s4b[TC];   // (y2,y2, h, h) per target
    __shared__ unsigned scol[TC];

    const int tid = threadIdx.x;
    const int tx  = tid & 15;           // 16 target columns (R13 layout)
    const int ty  = tid >> 4;           // 16 query groups of 8
    const int bid = blockIdx.x;

    scol[tid] = 0u;                     // identity (both halves)
    scol[tid + 256] = 0u;

    const int c0 = (int)(((long long)bid       * NCHUNK) / GRID);
    const int c1 = (int)(((long long)(bid + 1) * NCHUNK) / GRID);

    ull  m0p[4], m1p[4], m2p[4], x2p[4];   // 2 queries per packed reg (32 regs)
    float r[8];                             // scalar row-min accumulators
    int cur_strip = -1, cur_qbase = 0;

    for (int cid = c0; cid < c1; cid++) {
        const int b  = cid >> 8;        // 256 chunks per batch (32 qs x 8 tc)
        const int rr = cid & 255;
        const int qs = rr >> 3;
        const int tc = rr & 7;

        // ---- query strip management: flush 8 row mins, load 8 new queries ----
        const int strip = (b << 5) | qs;
        if (strip != cur_strip) {
            if (cur_strip >= 0) {
#pragma unroll
                for (int i = 0; i < 8; i++)
                    atomicMax(&g_key[cur_qbase + (ty << 3) + i], mkkey(r[i]));
            }
            cur_strip = strip;
            cur_qbase = (b << 12) + (qs << 7);
            // 8 points = 24 floats = 6 x float4 (96B, 16B-aligned)
            const float4* __restrict__ qv =
                (const float4*)(pred + (size_t)(cur_qbase + (ty << 3)) * 3);
            float4 f[6];
#pragma unroll
            for (int i = 0; i < 6; i++) f[i] = qv[i];
            const float* q = (const float*)f;
#pragma unroll
            for (int p = 0; p < 4; p++) {
                const float a0 = q[(2 * p) * 3 + 0], b0 = q[(2 * p + 1) * 3 + 0];
                const float a1 = q[(2 * p) * 3 + 1], b1 = q[(2 * p + 1) * 3 + 1];
                const float a2 = q[(2 * p) * 3 + 2], b2 = q[(2 * p + 1) * 3 + 2];
                m0p[p] = pk(-2.0f * a0, -2.0f * b0);
                m1p[p] = pk(-2.0f * a1, -2.0f * b1);
                m2p[p] = pk(-2.0f * a2, -2.0f * b2);
                x2p[p] = pk(a0 * a0 + a1 * a1 + a2 * a2,
                            b0 * b0 + b1 * b1 + b2 * b2);
                r[2 * p] = BIGF; r[2 * p + 1] = BIGF;
            }
        }

        // ---- fill target tile: 256 threads x 2 targets, duplicated lanes ----
        {
            const float* __restrict__ bp =
                targ + (size_t)((b << 12) + (tc << 9) + tid * 2) * 3;
            const float a0 = bp[0], a1 = bp[1], a2 = bp[2];
            const float b0 = bp[3], b1 = bp[4], b2 = bp[5];
            s4a[2 * tid]     = make_float4(a0, a0, a1, a1);
            s4b[2 * tid]     = make_float4(a2, a2,
                                           a0 * a0 + a1 * a1 + a2 * a2,
                                           a0 * a0 + a1 * a1 + a2 * a2);
            s4a[2 * tid + 1] = make_float4(b0, b0, b1, b1);
            s4b[2 * tid + 1] = make_float4(b2, b2,
                                           b0 * b0 + b1 * b1 + b2 * b2,
                                           b0 * b0 + b1 * b1 + b2 * b2);
        }
        __syncthreads();    // A: tile + scol(identity) visible

        // ---- main: 32 targets x 4 query-pairs = 256 pairs/thread ----
#pragma unroll
        for (int k = 0; k < 32; k++) {
            const int t = tx + (k << 4);
            const float4 ua = s4a[t];     // LDS.128: (y0,y0,y1,y1)
            const float4 ub = s4b[t];     // LDS.128: (y2,y2, h, h)
            const ull y0d = pk(ua.x, ua.y);   // aligned pairs (free remat)
            const ull y1d = pk(ua.z, ua.w);
            const ull y2d = pk(ub.x, ub.y);
            const ull hd  = pk(ub.z, ub.w);
            float ck = BIGF;
#pragma unroll
            for (int p = 0; p < 4; p++) {
                ull s, w;
                asm("add.rn.f32x2 %0, %1, %2;"     : "=l"(s) : "l"(x2p[p]), "l"(hd));
                asm("fma.rn.f32x2 %0, %1, %2, %3;" : "=l"(w) : "l"(m2p[p]), "l"(y2d), "l"(s));
                asm("fma.rn.f32x2 %0, %1, %2, %3;" : "=l"(w) : "l"(m1p[p]), "l"(y1d), "l"(w));
                asm("fma.rn.f32x2 %0, %1, %2, %3;" : "=l"(w) : "l"(m0p[p]), "l"(y0d), "l"(w));
                float wl, wh;
                asm("mov.b64 {%0, %1}, %2;" : "=f"(wl), "=f"(wh) : "l"(w));
                r[2 * p]     = fminf(r[2 * p],     wl);
                r[2 * p + 1] = fminf(r[2 * p + 1], wh);
                ck = fminf(ck, fminf(wl, wh));
            }
            // one return-less col merge per target (same ATOMS count as R13)
            atomicMax(&scol[t], mkkey(ck));
        }
        __syncthreads();    // B: scol complete; tile reads done

        // ---- two global return-less atomicMax per thread; reset own slots ----
        const int gb = (NBATCH * NPTS) + (b << 12) + (tc << 9);
        atomicMax(&g_key[gb + tid],       scol[tid]);
        atomicMax(&g_key[gb + tid + 256], scol[tid + 256]);
        scol[tid] = 0u;
        scol[tid + 256] = 0u;
    }

    // final row flush
    if (cur_strip >= 0) {
#pragma unroll
        for (int i = 0; i < 8; i++)
            atomicMax(&g_key[cur_qbase + (ty << 3) + i], mkkey(r[i]));
    }
}

// ---- launch 2: sqrt + mean; re-zeroes g_key; last block resets g_sum/g_done ----
__global__ void __launch_bounds__(P2_THREADS)
cd_reduce_kernel(float* __restrict__ out) {
    __shared__ float swsum[P2_THREADS / 32];
    const int tid = threadIdx.x;
    const int i = blockIdx.x * P2_THREADS + tid;     // 32768 threads, 1 uint4 each
    uint4* kp = reinterpret_cast<uint4*>(g_key);
    const uint4 kv = kp[i];
    float lsum = sqrtf(__uint_as_float(~kv.x)) + sqrtf(__uint_as_float(~kv.y))
               + sqrtf(__uint_as_float(~kv.z)) + sqrtf(__uint_as_float(~kv.w));
    kp[i] = make_uint4(0u, 0u, 0u, 0u);              // identity for next call
#pragma unroll
    for (int off = 16; off > 0; off >>= 1)
        lsum += __shfl_down_sync(0xFFFFFFFFu, lsum, off);
    const int lane = tid & 31;
    const int wid  = tid >> 5;
    if (lane == 0) swsum[wid] = lsum;
    __syncthreads();
    if (wid == 0) {
        float v = (lane < P2_THREADS / 32) ? swsum[lane] : 0.0f;
#pragma unroll
        for (int off = (P2_THREADS / 32) / 2; off > 0; off >>= 1)
            v += __shfl_down_sync(0xFFFFFFFFu, v, off);
        if (lane == 0) {
            atomicAdd(&g_sum, v);
            __threadfence();
            const unsigned rdone = atomicAdd(&g_done, 1u);
            if (rdone == P2_BLOCKS - 1) {
                out[0] = atomicAdd(&g_sum, 0.0f) * (1.0f / (float)(NBATCH * NPTS));
                g_sum = 0.0f;                        // reset for next replay
                g_done = 0u;
            }
        }
    }
}

extern "C" void kernel_launch(void* const* d_in, const int* in_sizes, int n_in,
                              void* d_out, int out_size) {
    const float* pred = (const float*)d_in[0];
    const float* targ = (const float*)d_in[1];
    float* out = (float*)d_out;
    cd_main_kernel<<<GRID, THREADS>>>(pred, targ);    // launch 1
    cd_reduce_kernel<<<P2_BLOCKS, P2_THREADS>>>(out); // launch 2
}

// round 16
// speedup vs baseline: 1.0491x; 1.0008x over previous
#include <cuda_runtime.h>

// Chamfer distance loss on (2,8,4096,3) fp32 clouds.
// Shared distance matrix (268M pairs): each pair updates the pred-side row-min
// and the targ-side col-min.  Min combining = atomicMax on inverted keys
// key = ~bits(max(d2,0)); identity 0 -> statically zero-init buffer; the
// reduce kernel re-zeroes slots after reading and its last block resets
// g_sum/g_done (stream-ordered for graph replay).
//
// Round-15: clean occupancy experiment. R13 schedule exactly (4096 chunks,
// 128-query strips, TC=512, same atomics/barriers), but queries are packed
// 2-per-f32x2 lane (32 query regs, was 64) and targets stored lane-duplicated
// in smem so packed operands load as aligned LDS.128 register pairs.
// ~70 regs -> 3 blocks/SM (6 warps/SMSP). Instruction mix per 2 pairs
// unchanged: 1 ADD2 + 3 FFMA2 + 4 FMNMX.

#define NPTS    4096
#define NBATCH  16
#define THREADS 256
#define GRID    444                     // 3 blocks/SM x 148
#define TC      512                     // targets per chunk
#define NCHUNK  (NBATCH * 32 * 8)       // 4096 chunks (32 qstrips x 8 tchunks)
#define NQTOT   (2 * NBATCH * NPTS)     // 131072
#define BIGF    3.4e38f

#define P2_BLOCKS 128
#define P2_THREADS 256

typedef unsigned long long ull;

__device__ unsigned g_key[NQTOT];       // zero-init; [0:65536)=pred rows, rest=targ cols
__device__ float    g_sum;              // zero-init; reset by reduce's last block
__device__ unsigned g_done;             // zero-init; reset by reduce's last block

__device__ __forceinline__ ull pk(float lo, float hi) {
    ull r; asm("mov.b64 %0, {%1, %2};" : "=l"(r) : "f"(lo), "f"(hi)); return r;
}
__device__ __forceinline__ unsigned mkkey(float d2) {
    return ~__float_as_uint(fmaxf(d2, 0.0f));
}

// ---- launch 1: pairwise mins ----
__global__ void __launch_bounds__(THREADS, 3)
cd_main_kernel(const float* __restrict__ pred, const float* __restrict__ targ) {
    __shared__ __align__(16) float4 s4a[TC];   // (y0,y0,y1,y1) per target
    __shared__ __align__(16) float4 s4b[TC];   // (y2,y2, h, h) per target
    __shared__ unsigned scol[TC];

    const int tid = threadIdx.x;
    const int tx  = tid & 15;           // 16 target columns (R13 layout)
    const int ty  = tid >> 4;           // 16 query groups of 8
    const int bid = blockIdx.x;

    scol[tid] = 0u;                     // identity (both halves)
    scol[tid + 256] = 0u;

    const int c0 = (int)(((long long)bid       * NCHUNK) / GRID);
    const int c1 = (int)(((long long)(bid + 1) * NCHUNK) / GRID);

    ull  m0p[4], m1p[4], m2p[4], x2p[4];   // 2 queries per packed reg (32 regs)
    float r[8];                             // scalar row-min accumulators
    int cur_strip = -1, cur_qbase = 0;

    for (int cid = c0; cid < c1; cid++) {
        const int b  = cid >> 8;        // 256 chunks per batch (32 qs x 8 tc)
        const int rr = cid & 255;
        const int qs = rr >> 3;
        const int tc = rr & 7;

        // ---- query strip management: flush 8 row mins, load 8 new queries ----
        const int strip = (b << 5) | qs;
        if (strip != cur_strip) {
            if (cur_strip >= 0) {
#pragma unroll
                for (int i = 0; i < 8; i++)
                    atomicMax(&g_key[cur_qbase + (ty << 3) + i], mkkey(r[i]));
            }
            cur_strip = strip;
            cur_qbase = (b << 12) + (qs << 7);
            // 8 points = 24 floats = 6 x float4 (96B, 16B-aligned)
            const float4* __restrict__ qv =
                (const float4*)(pred + (size_t)(cur_qbase + (ty << 3)) * 3);
            float4 f[6];
#pragma unroll
            for (int i = 0; i < 6; i++) f[i] = qv[i];
            const float* q = (const float*)f;
#pragma unroll
            for (int p = 0; p < 4; p++) {
                const float a0 = q[(2 * p) * 3 + 0], b0 = q[(2 * p + 1) * 3 + 0];
                const float a1 = q[(2 * p) * 3 + 1], b1 = q[(2 * p + 1) * 3 + 1];
                const float a2 = q[(2 * p) * 3 + 2], b2 = q[(2 * p + 1) * 3 + 2];
                m0p[p] = pk(-2.0f * a0, -2.0f * b0);
                m1p[p] = pk(-2.0f * a1, -2.0f * b1);
                m2p[p] = pk(-2.0f * a2, -2.0f * b2);
                x2p[p] = pk(a0 * a0 + a1 * a1 + a2 * a2,
                            b0 * b0 + b1 * b1 + b2 * b2);
                r[2 * p] = BIGF; r[2 * p + 1] = BIGF;
            }
        }

        // ---- fill target tile: 256 threads x 2 targets, duplicated lanes ----
        {
            const float* __restrict__ bp =
                targ + (size_t)((b << 12) + (tc << 9) + tid * 2) * 3;
            const float a0 = bp[0], a1 = bp[1], a2 = bp[2];
            const float b0 = bp[3], b1 = bp[4], b2 = bp[5];
            s4a[2 * tid]     = make_float4(a0, a0, a1, a1);
            s4b[2 * tid]     = make_float4(a2, a2,
                                           a0 * a0 + a1 * a1 + a2 * a2,
                                           a0 * a0 + a1 * a1 + a2 * a2);
            s4a[2 * tid + 1] = make_float4(b0, b0, b1, b1);
            s4b[2 * tid + 1] = make_float4(b2, b2,
                                           b0 * b0 + b1 * b1 + b2 * b2,
                                           b0 * b0 + b1 * b1 + b2 * b2);
        }
        __syncthreads();    // A: tile + scol(identity) visible

        // ---- main: 32 targets x 4 query-pairs = 256 pairs/thread ----
#pragma unroll
        for (int k = 0; k < 32; k++) {
            const int t = tx + (k << 4);
            const float4 ua = s4a[t];     // LDS.128: (y0,y0,y1,y1)
            const float4 ub = s4b[t];     // LDS.128: (y2,y2, h, h)
            const ull y0d = pk(ua.x, ua.y);   // aligned pairs (free remat)
            const ull y1d = pk(ua.z, ua.w);
            const ull y2d = pk(ub.x, ub.y);
            const ull hd  = pk(ub.z, ub.w);
            float ck = BIGF;
#pragma unroll
            for (int p = 0; p < 4; p++) {
                ull s, w;
                asm("add.rn.f32x2 %0, %1, %2;"     : "=l"(s) : "l"(x2p[p]), "l"(hd));
                asm("fma.rn.f32x2 %0, %1, %2, %3;" : "=l"(w) : "l"(m2p[p]), "l"(y2d), "l"(s));
                asm("fma.rn.f32x2 %0, %1, %2, %3;" : "=l"(w) : "l"(m1p[p]), "l"(y1d), "l"(w));
                asm("fma.rn.f32x2 %0, %1, %2, %3;" : "=l"(w) : "l"(m0p[p]), "l"(y0d), "l"(w));
                float wl, wh;
                asm("mov.b64 {%0, %1}, %2;" : "=f"(wl), "=f"(wh) : "l"(w));
                r[2 * p]     = fminf(r[2 * p],     wl);
                r[2 * p + 1] = fminf(r[2 * p + 1], wh);
                ck = fminf(ck, fminf(wl, wh));
            }
            // one return-less col merge per target (same ATOMS count as R13)
            atomicMax(&scol[t], mkkey(ck));
        }
        __syncthreads();    // B: scol complete; tile reads done

        // ---- two global return-less atomicMax per thread; reset own slots ----
        const int gb = (NBATCH * NPTS) + (b << 12) + (tc << 9);
        atomicMax(&g_key[gb + tid],       scol[tid]);
        atomicMax(&g_key[gb + tid + 256], scol[tid + 256]);
        scol[tid] = 0u;
        scol[tid + 256] = 0u;
    }

    // final row flush
    if (cur_strip >= 0) {
#pragma unroll
        for (int i = 0; i < 8; i++)
            atomicMax(&g_key[cur_qbase + (ty << 3) + i], mkkey(r[i]));
    }
}

// ---- launch 2: sqrt + mean; re-zeroes g_key; last block resets g_sum/g_done ----
__global__ void __launch_bounds__(P2_THREADS)
cd_reduce_kernel(float* __restrict__ out) {
    __shared__ float swsum[P2_THREADS / 32];
    const int tid = threadIdx.x;
    const int i = blockIdx.x * P2_THREADS + tid;     // 32768 threads, 1 uint4 each
    uint4* kp = reinterpret_cast<uint4*>(g_key);
    const uint4 kv = kp[i];
    float lsum = sqrtf(__uint_as_float(~kv.x)) + sqrtf(__uint_as_float(~kv.y))
               + sqrtf(__uint_as_float(~kv.z)) + sqrtf(__uint_as_float(~kv.w));
    kp[i] = make_uint4(0u, 0u, 0u, 0u);              // identity for next call
#pragma unroll
    for (int off = 16; off > 0; off >>= 1)
        lsum += __shfl_down_sync(0xFFFFFFFFu, lsum, off);
    const int lane = tid & 31;
    const int wid  = tid >> 5;
    if (lane == 0) swsum[wid] = lsum;
    __syncthreads();
    if (wid == 0) {
        float v = (lane < P2_THREADS / 32) ? swsum[lane] : 0.0f;
#pragma unroll
        for (int off = (P2_THREADS / 32) / 2; off > 0; off >>= 1)
            v += __shfl_down_sync(0xFFFFFFFFu, v, off);
        if (lane == 0) {
            atomicAdd(&g_sum, v);
            __threadfence();
            const unsigned rdone = atomicAdd(&g_done, 1u);
            if (rdone == P2_BLOCKS - 1) {
                out[0] = atomicAdd(&g_sum, 0.0f) * (1.0f / (float)(NBATCH * NPTS));
                g_sum = 0.0f;                        // reset for next replay
                g_done = 0u;
            }
        }
    }
}

extern "C" void kernel_launch(void* const* d_in, const int* in_sizes, int n_in,
                              void* d_out, int out_size) {
    const float* pred = (const float*)d_in[0];
    const float* targ = (const float*)d_in[1];
    float* out = (float*)d_out;
    cd_main_kernel<<<GRID, THREADS>>>(pred, targ);    // launch 1
    cd_reduce_kernel<<<P2_BLOCKS, P2_THREADS>>>(out); // launch 2
}

// round 17
// speedup vs baseline: 1.0495x; 1.0004x over previous
#include <cuda_runtime.h>

// Chamfer distance loss on (2,8,4096,3) fp32 clouds.
// Shared distance matrix (268M pairs): each pair updates the pred-side row-min
// and the targ-side col-min.  Min combining = atomicMax on inverted keys
// key = ~bits(max(d2,0)); identity 0 -> statically zero-init buffer; the
// reduce kernel re-zeroes slots after reading and its last block resets
// g_sum/g_done (stream-ordered for graph replay).
//
// Round-15: clean occupancy experiment. R13 schedule exactly (4096 chunks,
// 128-query strips, TC=512, same atomics/barriers), but queries are packed
// 2-per-f32x2 lane (32 query regs, was 64) and targets stored lane-duplicated
// in smem so packed operands load as aligned LDS.128 register pairs.
// ~70 regs -> 3 blocks/SM (6 warps/SMSP). Instruction mix per 2 pairs
// unchanged: 1 ADD2 + 3 FFMA2 + 4 FMNMX.

#define NPTS    4096
#define NBATCH  16
#define THREADS 256
#define GRID    444                     // 3 blocks/SM x 148
#define TC      512                     // targets per chunk
#define NCHUNK  (NBATCH * 32 * 8)       // 4096 chunks (32 qstrips x 8 tchunks)
#define NQTOT   (2 * NBATCH * NPTS)     // 131072
#define BIGF    3.4e38f

#define P2_BLOCKS 128
#define P2_THREADS 256

typedef unsigned long long ull;

__device__ unsigned g_key[NQTOT];       // zero-init; [0:65536)=pred rows, rest=targ cols
__device__ float    g_sum;              // zero-init; reset by reduce's last block
__device__ unsigned g_done;             // zero-init; reset by reduce's last block

__device__ __forceinline__ ull pk(float lo, float hi) {
    ull r; asm("mov.b64 %0, {%1, %2};" : "=l"(r) : "f"(lo), "f"(hi)); return r;
}
__device__ __forceinline__ unsigned mkkey(float d2) {
    return ~__float_as_uint(fmaxf(d2, 0.0f));
}

// ---- launch 1: pairwise mins ----
__global__ void __launch_bounds__(THREADS, 3)
cd_main_kernel(const float* __restrict__ pred, const float* __restrict__ targ) {
    __shared__ __align__(16) float4 s4a[TC];   // (y0,y0,y1,y1) per target
    __shared__ __align__(16) float4 s4b[TC];   // (y2,y2, h, h) per target
    __shared__ unsigned scol[TC];

    const int tid = threadIdx.x;
    const int tx  = tid & 15;           // 16 target columns (R13 layout)
    const int ty  = tid >> 4;           // 16 query groups of 8
    const int bid = blockIdx.x;

    scol[tid] = 0u;                     // identity (both halves)
    scol[tid + 256] = 0u;

    const int c0 = (int)(((long long)bid       * NCHUNK) / GRID);
    const int c1 = (int)(((long long)(bid + 1) * NCHUNK) / GRID);

    ull  m0p[4], m1p[4], m2p[4], x2p[4];   // 2 queries per packed reg (32 regs)
    float r[8];                             // scalar row-min accumulators
    int cur_strip = -1, cur_qbase = 0;

    for (int cid = c0; cid < c1; cid++) {
        const int b  = cid >> 8;        // 256 chunks per batch (32 qs x 8 tc)
        const int rr = cid & 255;
        const int qs = rr >> 3;
        const int tc = rr & 7;

        // ---- query strip management: flush 8 row mins, load 8 new queries ----
        const int strip = (b << 5) | qs;
        if (strip != cur_strip) {
            if (cur_strip >= 0) {
#pragma unroll
                for (int i = 0; i < 8; i++)
                    atomicMax(&g_key[cur_qbase + (ty << 3) + i], mkkey(r[i]));
            }
            cur_strip = strip;
            cur_qbase = (b << 12) + (qs << 7);
            // 8 points = 24 floats = 6 x float4 (96B, 16B-aligned)
            const float4* __restrict__ qv =
                (const float4*)(pred + (size_t)(cur_qbase + (ty << 3)) * 3);
            float4 f[6];
#pragma unroll
            for (int i = 0; i < 6; i++) f[i] = qv[i];
            const float* q = (const float*)f;
#pragma unroll
            for (int p = 0; p < 4; p++) {
                const float a0 = q[(2 * p) * 3 + 0], b0 = q[(2 * p + 1) * 3 + 0];
                const float a1 = q[(2 * p) * 3 + 1], b1 = q[(2 * p + 1) * 3 + 1];
                const float a2 = q[(2 * p) * 3 + 2], b2 = q[(2 * p + 1) * 3 + 2];
                m0p[p] = pk(-2.0f * a0, -2.0f * b0);
                m1p[p] = pk(-2.0f * a1, -2.0f * b1);
                m2p[p] = pk(-2.0f * a2, -2.0f * b2);
                x2p[p] = pk(a0 * a0 + a1 * a1 + a2 * a2,
                            b0 * b0 + b1 * b1 + b2 * b2);
                r[2 * p] = BIGF; r[2 * p + 1] = BIGF;
            }
        }

        // ---- fill target tile: 256 threads x 2 targets, duplicated lanes ----
        {
            const float* __restrict__ bp =
                targ + (size_t)((b << 12) + (tc << 9) + tid * 2) * 3;
            const float a0 = bp[0], a1 = bp[1], a2 = bp[2];
            const float b0 = bp[3], b1 = bp[4], b2 = bp[5];
            s4a[2 * tid]     = make_float4(a0, a0, a1, a1);
            s4b[2 * tid]     = make_float4(a2, a2,
                                           a0 * a0 + a1 * a1 + a2 * a2,
                                           a0 * a0 + a1 * a1 + a2 * a2);
            s4a[2 * tid + 1] = make_float4(b0, b0, b1, b1);
            s4b[2 * tid + 1] = make_float4(b2, b2,
                                           b0 * b0 + b1 * b1 + b2 * b2,
                                           b0 * b0 + b1 * b1 + b2 * b2);
        }
        __syncthreads();    // A: tile + scol(identity) visible

        // ---- main: 32 targets x 4 query-pairs = 256 pairs/thread ----
#pragma unroll
        for (int k = 0; k < 32; k++) {
            const int t = tx + (k << 4);
            const float4 ua = s4a[t];     // LDS.128: (y0,y0,y1,y1)
            const float4 ub = s4b[t];     // LDS.128: (y2,y2, h, h)
            const ull y0d = pk(ua.x, ua.y);   // aligned pairs (free remat)
            const ull y1d = pk(ua.z, ua.w);
            const ull y2d = pk(ub.x, ub.y);
            const ull hd  = pk(ub.z, ub.w);
            float ck = BIGF;
#pragma unroll
            for (int p = 0; p < 4; p++) {
                ull s, w;
                asm("add.rn.f32x2 %0, %1, %2;"     : "=l"(s) : "l"(x2p[p]), "l"(hd));
                asm("fma.rn.f32x2 %0, %1, %2, %3;" : "=l"(w) : "l"(m2p[p]), "l"(y2d), "l"(s));
                asm("fma.rn.f32x2 %0, %1, %2, %3;" : "=l"(w) : "l"(m1p[p]), "l"(y1d), "l"(w));
                asm("fma.rn.f32x2 %0, %1, %2, %3;" : "=l"(w) : "l"(m0p[p]), "l"(y0d), "l"(w));
                float wl, wh;
                asm("mov.b64 {%0, %1}, %2;" : "=f"(wl), "=f"(wh) : "l"(w));
                r[2 * p]     = fminf(r[2 * p],     wl);
                r[2 * p + 1] = fminf(r[2 * p + 1], wh);
                ck = fminf(ck, fminf(wl, wh));
            }
            // one return-less col merge per target (same ATOMS count as R13)
            atomicMax(&scol[t], mkkey(ck));
        }
        __syncthreads();    // B: scol complete; tile reads done

        // ---- two global return-less atomicMax per thread; reset own slots ----
        const int gb = (NBATCH * NPTS) + (b << 12) + (tc << 9);
        atomicMax(&g_key[gb + tid],       scol[tid]);
        atomicMax(&g_key[gb + tid + 256], scol[tid + 256]);
        scol[tid] = 0u;
        scol[tid + 256] = 0u;
    }

    // final row flush
    if (cur_strip >= 0) {
#pragma unroll
        for (int i = 0; i < 8; i++)
            atomicMax(&g_key[cur_qbase + (ty << 3) + i], mkkey(r[i]));
    }
}

// ---- launch 2: sqrt + mean; re-zeroes g_key; last block resets g_sum/g_done ----
__global__ void __launch_bounds__(P2_THREADS)
cd_reduce_kernel(float* __restrict__ out) {
    __shared__ float swsum[P2_THREADS / 32];
    const int tid = threadIdx.x;
    const int i = blockIdx.x * P2_THREADS + tid;     // 32768 threads, 1 uint4 each
    uint4* kp = reinterpret_cast<uint4*>(g_key);
    const uint4 kv = kp[i];
    float lsum = sqrtf(__uint_as_float(~kv.x)) + sqrtf(__uint_as_float(~kv.y))
               + sqrtf(__uint_as_float(~kv.z)) + sqrtf(__uint_as_float(~kv.w));
    kp[i] = make_uint4(0u, 0u, 0u, 0u);              // identity for next call
#pragma unroll
    for (int off = 16; off > 0; off >>= 1)
        lsum += __shfl_down_sync(0xFFFFFFFFu, lsum, off);
    const int lane = tid & 31;
    const int wid  = tid >> 5;
    if (lane == 0) swsum[wid] = lsum;
    __syncthreads();
    if (wid == 0) {
        float v = (lane < P2_THREADS / 32) ? swsum[lane] : 0.0f;
#pragma unroll
        for (int off = (P2_THREADS / 32) / 2; off > 0; off >>= 1)
            v += __shfl_down_sync(0xFFFFFFFFu, v, off);
        if (lane == 0) {
            atomicAdd(&g_sum, v);
            __threadfence();
            const unsigned rdone = atomicAdd(&g_done, 1u);
            if (rdone == P2_BLOCKS - 1) {
                out[0] = atomicAdd(&g_sum, 0.0f) * (1.0f / (float)(NBATCH * NPTS));
                g_sum = 0.0f;                        // reset for next replay
                g_done = 0u;
            }
        }
    }
}

extern "C" void kernel_launch(void* const* d_in, const int* in_sizes, int n_in,
                              void* d_out, int out_size) {
    const float* pred = (const float*)d_in[0];
    const float* targ = (const float*)d_in[1];
    float* out = (float*)d_out;
    cd_main_kernel<<<GRID, THREADS>>>(pred, targ);    // launch 1
    cd_reduce_kernel<<<P2_BLOCKS, P2_THREADS>>>(out); // launch 2
}